// round 2
// baseline (speedup 1.0000x reference)
#include <cuda_runtime.h>
#include <mma.h>
#include <math.h>

using namespace nvcuda;

#define SEQ   4096
#define DIM   512
#define BATCH 2
#define QSCALE 0.044194173824159216f  // 1/sqrt(512)

// ---------------- scratch (device globals; no allocations allowed) ----------
__device__ float g_Q[BATCH * SEQ * DIM];
__device__ float g_K[BATCH * SEQ * DIM];
__device__ float g_V[BATCH * SEQ * DIM];
__device__ float g_AT[BATCH * SEQ * DIM];  // attention output, transposed [b][d][s]

// =============================================================================
// tf32 WMMA GEMM (no bias):  C[m,n] = sum_k A[m,k] * W[n,k]
// M=8192, N=512, K=512. BM=BN=128, BK=16, 128 threads = 4 warps (2x2),
// warp tile 64x64 (4x4 m16n16k8 frags): 16 MMAs per 8 fragment loads.
// Double-buffered cp.async pipeline; smem rows padded to 24 floats.
// =============================================================================
#define TM 128
#define TN 128
#define TK 16
#define SST 24   // smem row stride in floats (96B: 32B-aligned rows, conflict-spread)

__device__ __forceinline__ void cp16(void* s, const void* g) {
    unsigned a = (unsigned)__cvta_generic_to_shared(s);
    asm volatile("cp.async.cg.shared.global [%0], [%1], 16;\n" :: "r"(a), "l"(g));
}

__global__ __launch_bounds__(128) void gemm_kernel(
    const float* __restrict__ A,
    const float* __restrict__ W0, const float* __restrict__ W1, const float* __restrict__ W2,
    float* __restrict__ C0, float* __restrict__ C1, float* __restrict__ C2)
{
    const float* W = (blockIdx.z == 0) ? W0 : (blockIdx.z == 1 ? W1 : W2);
    float*       C = (blockIdx.z == 0) ? C0 : (blockIdx.z == 1 ? C1 : C2);

    __shared__ float As[2][TM * SST];   // 12KB each
    __shared__ float Bs[2][TN * SST];   // total 48KB

    const int tid  = threadIdx.x;
    const int m0   = blockIdx.y * TM;
    const int n0   = blockIdx.x * TN;
    const int warp = tid >> 5;
    const int wr   = warp >> 1;   // 0..1
    const int wc   = warp & 1;    // 0..1

    wmma::fragment<wmma::accumulator, 16, 16, 8, float> c[4][4];
    #pragma unroll
    for (int i = 0; i < 4; i++)
        #pragma unroll
        for (int j = 0; j < 4; j++)
            wmma::fill_fragment(c[i][j], 0.0f);

    // stage loader: A tile 128x16 + B tile 128x16, 4+4 cp.async per thread
    auto load_stage = [&](int s, int k0) {
        #pragma unroll
        for (int t = 0; t < 4; t++) {
            int id = tid + t * 128;
            int row = id >> 2, c4 = id & 3;
            cp16(&As[s][row * SST + c4 * 4],
                 &A[(size_t)(m0 + row) * DIM + k0 + c4 * 4]);
        }
        #pragma unroll
        for (int t = 0; t < 4; t++) {
            int id = tid + t * 128;
            int row = id >> 2, c4 = id & 3;
            cp16(&Bs[s][row * SST + c4 * 4],
                 &W[(size_t)(n0 + row) * DIM + k0 + c4 * 4]);
        }
    };

    load_stage(0, 0);
    asm volatile("cp.async.commit_group;\n");

    const int NS = DIM / TK;  // 32
    for (int s = 0; s < NS; s++) {
        const int cur = s & 1;
        if (s + 1 < NS) {
            load_stage(cur ^ 1, (s + 1) * TK);
            asm volatile("cp.async.commit_group;\n");
            asm volatile("cp.async.wait_group 1;\n");
        } else {
            asm volatile("cp.async.wait_group 0;\n");
        }
        __syncthreads();

        #pragma unroll
        for (int kk = 0; kk < TK; kk += 8) {
            wmma::fragment<wmma::matrix_a, 16, 16, 8, wmma::precision::tf32, wmma::row_major> a[4];
            wmma::fragment<wmma::matrix_b, 16, 16, 8, wmma::precision::tf32, wmma::col_major> b[4];
            #pragma unroll
            for (int i = 0; i < 4; i++) {
                wmma::load_matrix_sync(a[i], &As[cur][(wr * 64 + i * 16) * SST + kk], SST);
                #pragma unroll
                for (int e = 0; e < a[i].num_elements; e++)
                    a[i].x[e] = wmma::__float_to_tf32(a[i].x[e]);
            }
            #pragma unroll
            for (int j = 0; j < 4; j++) {
                wmma::load_matrix_sync(b[j], &Bs[cur][(wc * 64 + j * 16) * SST + kk], SST);
                #pragma unroll
                for (int e = 0; e < b[j].num_elements; e++)
                    b[j].x[e] = wmma::__float_to_tf32(b[j].x[e]);
            }
            #pragma unroll
            for (int i = 0; i < 4; i++)
                #pragma unroll
                for (int j = 0; j < 4; j++)
                    wmma::mma_sync(c[i][j], a[i], b[j], c[i][j]);
        }
        __syncthreads();
    }

    // direct fragment store to global (bias handled elsewhere)
    #pragma unroll
    for (int i = 0; i < 4; i++)
        #pragma unroll
        for (int j = 0; j < 4; j++)
            wmma::store_matrix_sync(
                &C[(size_t)(m0 + wr * 64 + i * 16) * DIM + n0 + wc * 64 + j * 16],
                c[i][j], DIM, wmma::mem_row_major);
}

// =============================================================================
// Sparse attention: one CTA (512 threads) per query row.
// bq folded into q-row load; bk dropped (softmax shift-invariant);
// bv folded into output write (acc/l + bv since sum(p) = l).
// Output written TRANSPOSED AT[b][d][s] == reference transpose(1,2).reshape.
// =============================================================================
#define CHUNK 2048

__global__ __launch_bounds__(512) void attn_kernel(
    const float* __restrict__ Q, const float* __restrict__ K, const float* __restrict__ V,
    const float* __restrict__ mask, const float* __restrict__ bq, const float* __restrict__ bv,
    float* __restrict__ AT)
{
    __shared__ float qs[DIM];
    __shared__ int   idxs[CHUNK];
    __shared__ float ps[CHUNK];
    __shared__ int   cnt;
    __shared__ float red[16];
    __shared__ float bcast;

    const int tid = threadIdx.x;
    const int b   = blockIdx.x >> 12;
    const int q   = blockIdx.x & (SEQ - 1);

    // pre-scaled q row (+ bq) into smem
    qs[tid] = (Q[((size_t)b * SEQ + q) * DIM + tid] + bq[tid]) * QSCALE;

    const float* mrow = mask + ((size_t)b * SEQ + q) * SEQ;
    float m = -INFINITY, l = 0.0f, acc = 0.0f;

    for (int ch = 0; ch < SEQ / CHUNK; ++ch) {
        if (tid == 0) cnt = 0;
        __syncthreads();  // also covers qs visibility on first iter

        const int base = ch * CHUNK;
        #pragma unroll
        for (int j = tid; j < CHUNK; j += 512) {
            if (mrow[base + j] > 0.95f) {
                int p = atomicAdd(&cnt, 1);
                idxs[p] = base + j;
            }
        }
        __syncthreads();
        const int n = cnt;  // uniform

        if (n) {
            const int warp = tid >> 5, lane = tid & 31;
            const float4* qs4 = (const float4*)qs;
            // scores: one warp per kept key (16 warps)
            for (int i = warp; i < n; i += 16) {
                const float4* kr = (const float4*)&K[((size_t)b * SEQ + idxs[i]) * DIM];
                float s = 0.0f;
                #pragma unroll
                for (int u = 0; u < 4; u++) {
                    float4 kv = kr[lane + u * 32];
                    float4 qv = qs4[lane + u * 32];
                    s += kv.x * qv.x + kv.y * qv.y + kv.z * qv.z + kv.w * qv.w;
                }
                #pragma unroll
                for (int o = 16; o; o >>= 1) s += __shfl_xor_sync(0xffffffffu, s, o);
                if (lane == 0) ps[i] = s;
            }
            __syncthreads();

            // block max over ps[0..n)
            float cm = -INFINITY;
            for (int i = tid; i < n; i += 512) cm = fmaxf(cm, ps[i]);
            #pragma unroll
            for (int o = 16; o; o >>= 1) cm = fmaxf(cm, __shfl_xor_sync(0xffffffffu, cm, o));
            if (lane == 0) red[warp] = cm;
            __syncthreads();
            if (tid < 32) {
                float v2 = (tid < 16) ? red[tid] : -INFINITY;
                #pragma unroll
                for (int o = 8; o; o >>= 1) v2 = fmaxf(v2, __shfl_xor_sync(0xffffffffu, v2, o));
                if (tid == 0) bcast = v2;
            }
            __syncthreads();

            const float newm = fmaxf(m, bcast);
            const float r    = __expf(m - newm);  // m==-inf -> 0
            acc *= r; l *= r;
            m = newm;

            // exponentiate + block sum
            float cs = 0.0f;
            for (int i = tid; i < n; i += 512) {
                float p = __expf(ps[i] - m);
                ps[i] = p;
                cs += p;
            }
            #pragma unroll
            for (int o = 16; o; o >>= 1) cs += __shfl_xor_sync(0xffffffffu, cs, o);
            if (lane == 0) red[warp] = cs;
            __syncthreads();
            if (tid < 32) {
                float v2 = (tid < 16) ? red[tid] : 0.0f;
                #pragma unroll
                for (int o = 8; o; o >>= 1) v2 += __shfl_xor_sync(0xffffffffu, v2, o);
                if (tid == 0) bcast = v2;
            }
            __syncthreads();
            l += bcast;

            // accumulate P*V: 1 dim per thread; reads coalesced 2KB rows
            const float* Vb = V + (size_t)b * SEQ * DIM;
            int i = 0;
            for (; i + 3 < n; i += 4) {
                float p0 = ps[i], p1 = ps[i+1], p2 = ps[i+2], p3 = ps[i+3];
                const float* v0 = Vb + (size_t)idxs[i]   * DIM;
                const float* v1 = Vb + (size_t)idxs[i+1] * DIM;
                const float* v2p = Vb + (size_t)idxs[i+2] * DIM;
                const float* v3 = Vb + (size_t)idxs[i+3] * DIM;
                acc += p0 * v0[tid];
                acc += p1 * v1[tid];
                acc += p2 * v2p[tid];
                acc += p3 * v3[tid];
            }
            for (; i < n; i++)
                acc += ps[i] * Vb[(size_t)idxs[i] * DIM + tid];
        }
        __syncthreads();  // protect idxs/ps/cnt reuse next chunk
    }

    AT[((size_t)b * DIM + tid) * SEQ + q] = acc / l + bv[tid];
}

// ---------------- final bias add for output projection -----------------------
__global__ __launch_bounds__(256) void add_bias_kernel(
    float* __restrict__ out, const float* __restrict__ bo)
{
    int i = blockIdx.x * 256 + threadIdx.x;           // over 1M float4
    float4 v = ((float4*)out)[i];
    float4 bb = ((const float4*)bo)[i & 127];
    v.x += bb.x; v.y += bb.y; v.z += bb.z; v.w += bb.w;
    ((float4*)out)[i] = v;
}

// ---------------- launch ------------------------------------------------------
extern "C" void kernel_launch(void* const* d_in, const int* in_sizes, int n_in,
                              void* d_out, int out_size)
{
    const float* x    = (const float*)d_in[0];
    const float* mask = (const float*)d_in[1];
    const float* Wq   = (const float*)d_in[2];
    const float* bq   = (const float*)d_in[3];
    const float* Wk   = (const float*)d_in[4];
    // bk (d_in[5]) intentionally unused: softmax is shift-invariant in it
    const float* Wv   = (const float*)d_in[6];
    const float* bv   = (const float*)d_in[7];
    const float* Wo   = (const float*)d_in[8];
    const float* bo   = (const float*)d_in[9];

    float *Q, *K, *V, *AT;
    cudaGetSymbolAddress((void**)&Q,  g_Q);
    cudaGetSymbolAddress((void**)&K,  g_K);
    cudaGetSymbolAddress((void**)&V,  g_V);
    cudaGetSymbolAddress((void**)&AT, g_AT);

    // QKV projections (no bias; handled downstream)
    dim3 gq(DIM / TN, (BATCH * SEQ) / TM, 3);
    gemm_kernel<<<gq, 128>>>(x, Wq, Wk, Wv, Q, K, V);

    // sparse attention (folds bq, bv), output transposed into AT
    attn_kernel<<<BATCH * SEQ, 512>>>(Q, K, V, mask, bq, bv, AT);

    // output projection on the (implicitly shuffled) AT buffer
    dim3 go(DIM / TN, (BATCH * SEQ) / TM, 1);
    gemm_kernel<<<go, 128>>>(AT, Wo, Wo, Wo,
                             (float*)d_out, (float*)d_out, (float*)d_out);

    // + bo
    add_bias_kernel<<<(BATCH * SEQ * DIM / 4) / 256, 256>>>((float*)d_out, bo);
}